// round 11
// baseline (speedup 1.0000x reference)
#include <cuda_runtime.h>
#include <cuda_bf16.h>

#define P_TOT  61440
#define NTHR   256
#define TPI    960          /* 64-pixel tiles per image */
#define NCTA   5760
#define W0S    30.0f
#define QA     16256.0f

#define BND_A  0.010206207261596576   /* sqrt(6/64)/30  */
#define BND_B  0.005103103630798288   /* sqrt(6/256)/30 */
#define C1A    ((float)(16384.0*BND_A/264257536.0))
#define C2A    ((float)(  128.0*BND_A/264257536.0))
#define C1B    ((float)(16384.0*BND_B/264257536.0))
#define C2B    ((float)(  128.0*BND_B/264257536.0))

/* smem map (bytes) */
#define AB0     0        /* int8 act buf0: limb1 @0, limb0 @+16384 (64 rows x 256B) */
#define AB1     32768    /* int8 act buf1; aliased by L0 bf16 input: hi @AB1, lo @AB1+16384 */
#define WB0     65536    /* 8KB weight stage buf */
#define WB1     73728
#define SBO     81920    /* 960 float biases */
#define SMEM_TOT 85760

/* L0 bf16 weights: 5 k16-chunks x [hi: 64n x 32B swz | lo: same] (elems) */
static __device__ __align__(16) __nv_bfloat16 g_w16[10240];
/* L1..L5 int8 weights: per (half,k32chunk) block [q1: nloc x 32B swz | q0: same] */
static __device__ __align__(16) signed char g_w8[335872];

__global__ void prep_kernel(const float* __restrict__ w0, const float* __restrict__ w1,
                            const float* __restrict__ w2, const float* __restrict__ w3,
                            const float* __restrict__ w4, const float* __restrict__ w5)
{
    int l = blockIdx.y;
    if (l == 0){
        for (int idx = blockIdx.x*blockDim.x + threadIdx.x; idx < 5120; idx += gridDim.x*blockDim.x){
            int kin = idx & 15, n = (idx >> 4) & 63, c = idx >> 10;
            int k = c*16 + kin;
            float v = (k < 65) ? w0[n*65 + k] : 0.0f;
            __nv_bfloat16 h  = __float2bfloat16(v);
            __nv_bfloat16 lo = __float2bfloat16(v - __bfloat162float(h));
            int eoff = n*16 + ((((kin>>3) ^ ((n>>2)&1))) << 3) + (kin & 7);
            g_w16[c*2048 + eoff]        = h;
            g_w16[c*2048 + 1024 + eoff] = lo;
        }
        return;
    }
    const int    KK[5]   = {64,64,256,256,256};
    const int    HL[5]   = {1,2,2,2,1};
    const int    NLOC[5] = {64,128,128,128,64};
    const int    KC[5]   = {2,2,8,8,8};
    const int    GOFF[5] = {0,8192,40960,172032,303104};
    const double BD[5]   = {BND_A,BND_A,BND_B,BND_B,BND_B};
    int li = l - 1;
    const float* w = (li==0)?w1:(li==1)?w2:(li==2)?w3:(li==3)?w4:w5;
    int nloc = NLOC[li], K = KK[li], kc = KC[li];
    int total = HL[li]*kc*nloc*32;
    float inv = (float)(16256.0 / BD[li]);
    for (int idx = blockIdx.x*blockDim.x + threadIdx.x; idx < total; idx += gridDim.x*blockDim.x){
        int kin = idx & 31;
        int nl  = (idx >> 5) % nloc;
        int blk = idx / (32*nloc);
        int c = blk % kc, h = blk / kc;
        int n = h*nloc + nl;
        int k = c*32 + kin;
        float v = w[n*K + k];
        int q  = __float2int_rn(v * inv);
        int q1 = (q + 64) >> 7;
        int q0 = q - q1*128;
        int eoff = nl*32 + ((((kin>>4) ^ ((nl>>2)&1))) << 4) + (kin & 15);
        int base = GOFF[li] + blk*(nloc*64);
        g_w8[base + eoff]           = (signed char)q1;
        g_w8[base + nloc*32 + eoff] = (signed char)q0;
    }
}

/* ---------------- helpers ---------------- */
__device__ __forceinline__ unsigned s2u(const void* p){
    unsigned a;
    asm("{ .reg .u64 t; cvta.to.shared.u64 t, %1; cvt.u32.u64 %0, t; }" : "=r"(a) : "l"(p));
    return a;
}
__device__ __forceinline__ void cp16(unsigned dst, const void* src){
    asm volatile("cp.async.cg.shared.global [%0], [%1], 16;" :: "r"(dst), "l"(src));
}
__device__ __forceinline__ void cp_commit(){ asm volatile("cp.async.commit_group;"); }
__device__ __forceinline__ void cp_wait0(){ asm volatile("cp.async.wait_group 0;"); }
__device__ __forceinline__ void stage(unsigned dst, const char* src, int bytes, int tid){
    for (int i = tid*16; i < bytes; i += NTHR*16) cp16(dst + i, src + i);
}
__device__ __forceinline__ void ldmx4(unsigned* r, unsigned addr){
    asm volatile("ldmatrix.sync.aligned.m8n8.x4.shared.b16 {%0,%1,%2,%3}, [%4];"
        : "=r"(r[0]), "=r"(r[1]), "=r"(r[2]), "=r"(r[3]) : "r"(addr));
}
__device__ __forceinline__ void mma_bf16(float* c, const unsigned* a, unsigned b0, unsigned b1){
    asm volatile("mma.sync.aligned.m16n8k16.row.col.f32.bf16.bf16.f32 "
        "{%0,%1,%2,%3}, {%4,%5,%6,%7}, {%8,%9}, {%0,%1,%2,%3};"
        : "+f"(c[0]), "+f"(c[1]), "+f"(c[2]), "+f"(c[3])
        : "r"(a[0]), "r"(a[1]), "r"(a[2]), "r"(a[3]), "r"(b0), "r"(b1));
}
__device__ __forceinline__ void imma(int* c, const unsigned* a, unsigned b0, unsigned b1){
    asm volatile("mma.sync.aligned.m16n8k32.row.col.s32.s8.s8.s32 "
        "{%0,%1,%2,%3}, {%4,%5,%6,%7}, {%8,%9}, {%0,%1,%2,%3};"
        : "+r"(c[0]), "+r"(c[1]), "+r"(c[2]), "+r"(c[3])
        : "r"(a[0]), "r"(a[1]), "r"(a[2]), "r"(a[3]), "r"(b0), "r"(b1));
}
__device__ __forceinline__ void sts16(unsigned addr, unsigned v){
    asm volatile("st.shared.u16 [%0], %1;" :: "r"(addr), "h"((unsigned short)v));
}

/* quantize a pair of sin outputs (cols n, n+1, n even) and store both limbs */
__device__ __forceinline__ void qstore(unsigned smb, unsigned aout, int r, int n, float s0, float s1){
    int q = __float2int_rn(s0*QA); int q1 = (q + 64) >> 7; int q0 = q - q1*128;
    int p = __float2int_rn(s1*QA); int p1 = (p + 64) >> 7; int p0 = p - p1*128;
    unsigned off = (unsigned)(r*256) + ((((unsigned)(n>>4) ^ (unsigned)(r&7))) << 4) + (unsigned)(n & 15);
    sts16(smb + aout + off,         (unsigned)((q1 & 0xFF) | ((p1 & 0xFF) << 8)));
    sts16(smb + aout + 16384 + off, (unsigned)((q0 & 0xFF) | ((p0 & 0xFF) << 8)));
}

/* ---- one int8 half-layer: reads A(ain, K=kc*32 int8 cols), produces cols [hoff, hoff+nloc) ---- */
template<int NF, bool LAST>
__device__ __forceinline__ void half8(unsigned smb,
    unsigned ain, unsigned aout, const char* gw, int kc, int nloc, int hoff,
    float C1, float C2, const float* sbL,
    const char* gnext, int nbytes, int& buf,
    int wm, int wn, int lane, int tid, float* outp)
{
    const int gid   = lane >> 2, tig = lane & 3;
    const int row_a = (lane & 7) + ((lane >> 3) & 1)*8;
    const int ca    = lane >> 4;
    const int n_off = (lane & 7) + (lane >> 4)*8;
    const int cb    = (lane >> 3) & 1;
    const int cbytes = nloc*64;

    int hh[2][NF][4], xx[2][NF][4];
#pragma unroll
    for (int i = 0; i < 2; i++)
#pragma unroll
        for (int j = 0; j < NF; j++)
#pragma unroll
            for (int q = 0; q < 4; q++){ hh[i][j][q] = 0; xx[i][j][q] = 0; }

    int cur = buf;
    for (int c = 0; c < kc; c++){
        cp_wait0();
        __syncthreads();
        if (c + 1 < kc){
            stage(smb + (cur ? WB0 : WB1), gw + (size_t)(c+1)*cbytes, cbytes, tid);
            cp_commit();
        }
        unsigned wb  = smb + (cur ? WB1 : WB0);
        unsigned wlo = wb + (unsigned)(nloc*32);

        unsigned a1f[2][4], a0f[2][4];
#pragma unroll
        for (int mt = 0; mt < 2; mt++){
            int row = wm*32 + mt*16 + row_a;
            unsigned off = (unsigned)(row*256) + ((((unsigned)(2*c + ca) ^ (unsigned)(row & 7))) << 4);
            ldmx4(a1f[mt], smb + ain + off);
            ldmx4(a0f[mt], smb + ain + 16384 + off);
        }
#pragma unroll
        for (int np = 0; np < NF/2; np++){
            int nl = wn*(8*NF) + np*16 + n_off;
            unsigned off = (unsigned)(nl*32) + ((((unsigned)cb ^ (unsigned)((nl >> 2) & 1))) << 4);
            unsigned b1f[4], b0f[4];
            ldmx4(b1f, wb + off);
            ldmx4(b0f, wlo + off);
#pragma unroll
            for (int mt = 0; mt < 2; mt++){
                imma(hh[mt][2*np],   a1f[mt], b1f[0], b1f[1]);
                imma(hh[mt][2*np+1], a1f[mt], b1f[2], b1f[3]);
                imma(xx[mt][2*np],   a1f[mt], b0f[0], b0f[1]);
                imma(xx[mt][2*np],   a0f[mt], b1f[0], b1f[1]);
                imma(xx[mt][2*np+1], a1f[mt], b0f[2], b0f[3]);
                imma(xx[mt][2*np+1], a0f[mt], b1f[2], b1f[3]);
            }
        }
        cur ^= 1;
    }
    buf = cur;
    __syncthreads();
    if (gnext){
        stage(smb + (cur ? WB1 : WB0), gnext, nbytes, tid);
        cp_commit();
    }

#pragma unroll
    for (int mt = 0; mt < 2; mt++){
#pragma unroll
        for (int j = 0; j < NF; j++){
            int n  = hoff + wn*(8*NF) + j*8 + 2*tig;
            int r0 = wm*32 + mt*16 + gid;
            float v0 = C1*(float)hh[mt][j][0] + C2*(float)xx[mt][j][0] + sbL[n];
            float v1 = C1*(float)hh[mt][j][1] + C2*(float)xx[mt][j][1] + sbL[n+1];
            float v2 = C1*(float)hh[mt][j][2] + C2*(float)xx[mt][j][2] + sbL[n];
            float v3 = C1*(float)hh[mt][j][3] + C2*(float)xx[mt][j][3] + sbL[n+1];
            if (!LAST){
                qstore(smb, aout, r0,     n, __sinf(W0S*v0), __sinf(W0S*v1));
                qstore(smb, aout, r0 + 8, n, __sinf(W0S*v2), __sinf(W0S*v3));
            } else {
                outp[(size_t)n*P_TOT     + r0]     = v0;
                outp[(size_t)(n+1)*P_TOT + r0]     = v1;
                outp[(size_t)n*P_TOT     + r0 + 8] = v2;
                outp[(size_t)(n+1)*P_TOT + r0 + 8] = v3;
            }
        }
    }
}

/* ---- layer 0: bf16 hi/lo 3-pass, K=80, N=64; A0 bf16 @AB1, out int8 -> AB0 ---- */
__device__ __forceinline__ void lay0(unsigned smb, const float* sbL, int& buf,
                                     int wm, int wn, int lane, int tid)
{
    const int gid   = lane >> 2, tig = lane & 3;
    const int row_a = (lane & 7) + ((lane >> 3) & 1)*8;
    const int ca    = lane >> 4;
    const int n_off = (lane & 7) + (lane >> 4)*8;
    const int cb    = (lane >> 3) & 1;

    float fa[2][2][4];
#pragma unroll
    for (int i = 0; i < 2; i++)
#pragma unroll
        for (int j = 0; j < 2; j++)
#pragma unroll
            for (int q = 0; q < 4; q++) fa[i][j][q] = 0.0f;

    int cur = buf;
    for (int s = 0; s < 5; s++){
        cp_wait0();
        __syncthreads();
        if (s + 1 < 5){
            stage(smb + (cur ? WB0 : WB1), (const char*)(g_w16 + (s+1)*2048), 4096, tid);
            cp_commit();
        }
        unsigned wb  = smb + (cur ? WB1 : WB0);
        unsigned wlo = wb + 2048;

        unsigned ah[2][4], al[2][4];
#pragma unroll
        for (int mt = 0; mt < 2; mt++){
            int row = wm*32 + mt*16 + row_a;
            unsigned off = (unsigned)(row*256) + ((((unsigned)(2*s + ca) ^ (unsigned)(row & 7))) << 4);
            ldmx4(ah[mt], smb + AB1 + off);
            ldmx4(al[mt], smb + AB1 + 16384 + off);
        }
        {
            int nl = wn*16 + n_off;
            unsigned off = (unsigned)(nl*32) + ((((unsigned)cb ^ (unsigned)((nl >> 2) & 1))) << 4);
            unsigned bh[4], bl[4];
            ldmx4(bh, wb + off);
            ldmx4(bl, wlo + off);
#pragma unroll
            for (int mt = 0; mt < 2; mt++){
                mma_bf16(fa[mt][0], ah[mt], bh[0], bh[1]);
                mma_bf16(fa[mt][0], al[mt], bh[0], bh[1]);
                mma_bf16(fa[mt][0], ah[mt], bl[0], bl[1]);
                mma_bf16(fa[mt][1], ah[mt], bh[2], bh[3]);
                mma_bf16(fa[mt][1], al[mt], bh[2], bh[3]);
                mma_bf16(fa[mt][1], ah[mt], bl[2], bl[3]);
            }
        }
        cur ^= 1;
    }
    buf = cur;
    __syncthreads();
    /* prefetch L1 chunk0 (4KB) */
    stage(smb + (cur ? WB1 : WB0), (const char*)g_w8, 4096, tid);
    cp_commit();

#pragma unroll
    for (int mt = 0; mt < 2; mt++){
#pragma unroll
        for (int j = 0; j < 2; j++){
            int n  = wn*16 + j*8 + 2*tig;
            int r0 = wm*32 + mt*16 + gid;
            float v0 = fa[mt][j][0] + sbL[n];
            float v1 = fa[mt][j][1] + sbL[n+1];
            float v2 = fa[mt][j][2] + sbL[n];
            float v3 = fa[mt][j][3] + sbL[n+1];
            qstore(smb, AB0, r0,     n, __sinf(W0S*v0), __sinf(W0S*v1));
            qstore(smb, AB0, r0 + 8, n, __sinf(W0S*v2), __sinf(W0S*v3));
        }
    }
}

__global__ void __launch_bounds__(NTHR, 2)
mlp_i8_kernel(const float* __restrict__ feat, const float* __restrict__ times,
              const float* __restrict__ b0, const float* __restrict__ b1,
              const float* __restrict__ b2, const float* __restrict__ b3,
              const float* __restrict__ b4, const float* __restrict__ b5,
              float* __restrict__ out)
{
    extern __shared__ char smp[];
    float* sb = (float*)(smp + SBO);
    const unsigned smb = s2u(smp);
    const int tid  = threadIdx.x;
    const int wid  = tid >> 5;
    const int lane = tid & 31;
    const int wm   = wid & 1;       /* 2 M-groups of 32 rows */
    const int wn   = wid >> 1;      /* 4 N-groups */

    const int tile = blockIdx.x;
    const int img  = tile / TPI;
    const int p0   = (tile - img*TPI) * 64;
    const int cidx = img >> 1, bidx = img & 1;
    const float tval = times[cidx];

    /* biases */
    if (tid < 64){ sb[tid] = b0[tid]; sb[64+tid] = b1[tid]; sb[896+tid] = b5[tid]; }
    for (int i = tid; i < 256; i += NTHR){ sb[128+i] = b2[i]; sb[384+i] = b3[i]; sb[640+i] = b4[i]; }

    /* stage L0 chunk0 */
    stage(smb + WB0, (const char*)g_w16, 4096, tid);
    cp_commit();

    /* build A0 bf16 hi/lo: 64 rows x cols 0..79 (64 feats, t, zeros), pitch 256B */
    {
        const float* fb = feat + (size_t)(bidx*64)*P_TOT + p0;
        for (int idx = tid; idx < 5120; idx += NTHR){
            int r = idx & 63, ch = idx >> 6;
            float v = (ch < 64) ? fb[(size_t)ch*P_TOT + r] : ((ch == 64) ? tval : 0.0f);
            __nv_bfloat16 h  = __float2bfloat16(v);
            __nv_bfloat16 lo = __float2bfloat16(v - __bfloat162float(h));
            unsigned off = (unsigned)(r*256) + ((((unsigned)(ch>>3) ^ (unsigned)(r&7))) << 4) + (unsigned)((ch & 7)*2);
            *(unsigned short*)(smp + AB1 + off)         = *(unsigned short*)&h;
            *(unsigned short*)(smp + AB1 + 16384 + off) = *(unsigned short*)&lo;
        }
    }

    float* outp = out + (size_t)img*64*P_TOT + p0;
    const char* gw = (const char*)g_w8;
    int buf = 0;

    lay0(smb, sb + 0, buf, wm, wn, lane, tid);                                    /* -> AB0 */

    half8<2,false>(smb, AB0, AB1, gw + 0,             2,  64, 0,   C1A, C2A, sb+64,
                   gw + 8192, 8192, buf, wm, wn, lane, tid, outp);                /* L1 -> AB1 */
    half8<4,false>(smb, AB1, AB0, gw + 8192,          2, 128, 0,   C1A, C2A, sb+128,
                   gw + 8192 + 16384, 8192, buf, wm, wn, lane, tid, outp);        /* L2 h0 */
    half8<4,false>(smb, AB1, AB0, gw + 8192 + 16384,  2, 128, 128, C1A, C2A, sb+128,
                   gw + 40960, 8192, buf, wm, wn, lane, tid, outp);               /* L2 h1 -> AB0 */
    half8<4,false>(smb, AB0, AB1, gw + 40960,         8, 128, 0,   C1B, C2B, sb+384,
                   gw + 40960 + 65536, 8192, buf, wm, wn, lane, tid, outp);       /* L3 h0 */
    half8<4,false>(smb, AB0, AB1, gw + 40960 + 65536, 8, 128, 128, C1B, C2B, sb+384,
                   gw + 172032, 8192, buf, wm, wn, lane, tid, outp);              /* L3 h1 -> AB1 */
    half8<4,false>(smb, AB1, AB0, gw + 172032,        8, 128, 0,   C1B, C2B, sb+640,
                   gw + 172032 + 65536, 8192, buf, wm, wn, lane, tid, outp);      /* L4 h0 */
    half8<4,false>(smb, AB1, AB0, gw + 172032 + 65536,8, 128, 128, C1B, C2B, sb+640,
                   gw + 303104, 4096, buf, wm, wn, lane, tid, outp);              /* L4 h1 -> AB0 */
    half8<2,true >(smb, AB0, 0,   gw + 303104,        8,  64, 0,   C1B, C2B, sb+896,
                   (const char*)0, 0, buf, wm, wn, lane, tid, outp);              /* L5 -> out */
}

extern "C" void kernel_launch(void* const* d_in, const int* in_sizes, int n_in,
                              void* d_out, int out_size)
{
    const float* feat  = (const float*)d_in[0];
    const float* times = (const float*)d_in[1];
    const float* w0 = (const float*)d_in[2];
    const float* b0 = (const float*)d_in[3];
    const float* w1 = (const float*)d_in[4];
    const float* b1 = (const float*)d_in[5];
    const float* w2 = (const float*)d_in[6];
    const float* b2 = (const float*)d_in[7];
    const float* w3 = (const float*)d_in[8];
    const float* b3 = (const float*)d_in[9];
    const float* w4 = (const float*)d_in[10];
    const float* b4 = (const float*)d_in[11];
    const float* w5 = (const float*)d_in[12];
    const float* b5 = (const float*)d_in[13];
    float* out = (float*)d_out;

    cudaFuncSetAttribute(mlp_i8_kernel, cudaFuncAttributeMaxDynamicSharedMemorySize, SMEM_TOT);

    prep_kernel<<<dim3(64, 6), 256>>>(w0, w1, w2, w3, w4, w5);
    mlp_i8_kernel<<<NCTA, NTHR, SMEM_TOT>>>(feat, times, b0, b1, b2, b3, b4, b5, out);
}

// round 16
// speedup vs baseline: 2.6779x; 2.6779x over previous
#include <cuda_runtime.h>
#include <cuda_bf16.h>

#define P_TOT  61440
#define NTHR   256
#define TPI    960
#define NCTA   5760
#define W0S    30.0f

/* smem map (bytes) */
#define AHI     0        /* 64 rows x 512B (256 bf16 cols, swizzled) */
#define ALO     32768
#define WB0     65536    /* 16KB weight chunk buf */
#define WB1     81920
#define SBO     98304    /* 960 float biases */
#define SMEM_TOT 102144

/* bf16 weights, hi/lo split, k16-chunk layout:
   chunk c of layer: [hi: N rows x 32B swz | lo: same], chunk_bytes = N*64 */
static __device__ __align__(16) __nv_bfloat16 g_w[346112];

__global__ void prep_kernel(const float* __restrict__ w0, const float* __restrict__ w1,
                            const float* __restrict__ w2, const float* __restrict__ w3,
                            const float* __restrict__ w4, const float* __restrict__ w5)
{
    const int K[6]    = {65,64,64,256,256,256};
    const int N[6]    = {64,64,256,256,256,64};
    const int KC[6]   = {5,4,4,16,16,16};
    const int GOFF[6] = {0,10240,18432,51200,182272,313344};   /* elems */
    int l = blockIdx.y;
    const float* w = (l==0)?w0:(l==1)?w1:(l==2)?w2:(l==3)?w3:(l==4)?w4:w5;
    int Nl = N[l], Kl = K[l];
    int total = KC[l]*Nl*16;
    for (int idx = blockIdx.x*blockDim.x + threadIdx.x; idx < total; idx += gridDim.x*blockDim.x){
        int kin = idx & 15;
        int n   = (idx >> 4) % Nl;
        int c   = idx / (16*Nl);
        int k   = c*16 + kin;
        float v = (k < Kl) ? w[n*Kl + k] : 0.0f;
        __nv_bfloat16 h  = __float2bfloat16(v);
        __nv_bfloat16 lo = __float2bfloat16(v - __bfloat162float(h));
        int eoff = n*16 + ((((kin>>3) ^ ((n>>2)&1))) << 3) + (kin & 7);
        int base = GOFF[l] + c*(Nl*32);
        g_w[base + eoff]          = h;
        g_w[base + Nl*16 + eoff]  = lo;
    }
}

/* ---------------- helpers ---------------- */
__device__ __forceinline__ unsigned s2u(const void* p){
    unsigned a;
    asm("{ .reg .u64 t; cvta.to.shared.u64 t, %1; cvt.u32.u64 %0, t; }" : "=r"(a) : "l"(p));
    return a;
}
__device__ __forceinline__ void cp16(unsigned dst, const void* src){
    asm volatile("cp.async.cg.shared.global [%0], [%1], 16;" :: "r"(dst), "l"(src));
}
__device__ __forceinline__ void cp_commit(){ asm volatile("cp.async.commit_group;"); }
__device__ __forceinline__ void cp_wait0(){ asm volatile("cp.async.wait_group 0;"); }
__device__ __forceinline__ void stage(unsigned dst, const char* src, int bytes, int tid){
    for (int i = tid*16; i < bytes; i += NTHR*16) cp16(dst + i, src + i);
}
__device__ __forceinline__ void ldmx4(unsigned* r, unsigned addr){
    asm volatile("ldmatrix.sync.aligned.m8n8.x4.shared.b16 {%0,%1,%2,%3}, [%4];"
        : "=r"(r[0]), "=r"(r[1]), "=r"(r[2]), "=r"(r[3]) : "r"(addr));
}
__device__ __forceinline__ void mma_bf16(float* c, const unsigned* a, unsigned b0, unsigned b1){
    asm volatile("mma.sync.aligned.m16n8k16.row.col.f32.bf16.bf16.f32 "
        "{%0,%1,%2,%3}, {%4,%5,%6,%7}, {%8,%9}, {%0,%1,%2,%3};"
        : "+f"(c[0]), "+f"(c[1]), "+f"(c[2]), "+f"(c[3])
        : "r"(a[0]), "r"(a[1]), "r"(a[2]), "r"(a[3]), "r"(b0), "r"(b1));
}
__device__ __forceinline__ unsigned pack_bf2(float hi_val, float lo_val){
    unsigned r;  /* d.lo = lo_val, d.hi = hi_val */
    asm("cvt.rn.bf16x2.f32 %0, %1, %2;" : "=r"(r) : "f"(hi_val), "f"(lo_val));
    return r;
}
__device__ __forceinline__ float bflo(unsigned u){ return __bfloat162float(((__nv_bfloat162*)&u)->x); }
__device__ __forceinline__ float bfhi(unsigned u){ return __bfloat162float(((__nv_bfloat162*)&u)->y); }

/* one layer: A in smem (AHI/ALO, 64 rows x 512B), in-place epilogue update.
   kc = number of k16 chunks, Nl = output cols, chunk staged per k-step. */
template<int NF, bool LAST>
__device__ __forceinline__ void lay(unsigned smb, char* smp,
    const char* gw, int kc, int Nl, const float* sbL,
    const char* gnext, int nbytes, int& buf,
    int wm, int wn, int lane, int tid, float* outp)
{
    const int gid   = lane >> 2, tig = lane & 3;
    const int row_a = (lane & 7) + ((lane >> 3) & 1)*8;
    const int ca    = lane >> 4;
    const int n_off = (lane & 7) + (lane >> 4)*8;
    const int cb    = (lane >> 3) & 1;
    const int cbytes = Nl*64;

    float acc[2][NF][4];
#pragma unroll
    for (int i = 0; i < 2; i++)
#pragma unroll
        for (int j = 0; j < NF; j++)
#pragma unroll
            for (int q = 0; q < 4; q++) acc[i][j][q] = 0.0f;

    int cur = buf;
    for (int c = 0; c < kc; c++){
        cp_wait0();
        __syncthreads();
        if (c + 1 < kc){
            stage(smb + (cur ? WB0 : WB1), gw + (size_t)(c+1)*cbytes, cbytes, tid);
            cp_commit();
        }
        unsigned wb  = smb + (cur ? WB1 : WB0);
        unsigned wlo = wb + (unsigned)(Nl*32);

        unsigned ah[2][4], al[2][4];
#pragma unroll
        for (int mt = 0; mt < 2; mt++){
            int row = wm*32 + mt*16 + row_a;
            unsigned off = (unsigned)(row*512) + ((((unsigned)(2*c + ca) ^ (unsigned)(row & 7))) << 4);
            ldmx4(ah[mt], smb + AHI + off);
            ldmx4(al[mt], smb + ALO + off);
        }
#pragma unroll
        for (int np = 0; np < NF/2; np++){
            int nl = wn*(8*NF) + np*16 + n_off;
            unsigned off = (unsigned)(nl*32) + ((((unsigned)cb ^ (unsigned)((nl >> 2) & 1))) << 4);
            unsigned bh[4], bl[4];
            ldmx4(bh, wb + off);
            ldmx4(bl, wlo + off);
#pragma unroll
            for (int mt = 0; mt < 2; mt++){
                mma_bf16(acc[mt][2*np],   ah[mt], bh[0], bh[1]);
                mma_bf16(acc[mt][2*np],   al[mt], bh[0], bh[1]);
                mma_bf16(acc[mt][2*np],   ah[mt], bl[0], bl[1]);
                mma_bf16(acc[mt][2*np+1], ah[mt], bh[2], bh[3]);
                mma_bf16(acc[mt][2*np+1], al[mt], bh[2], bh[3]);
                mma_bf16(acc[mt][2*np+1], ah[mt], bl[2], bl[3]);
            }
        }
        cur ^= 1;
    }
    buf = cur;
    __syncthreads();                 /* all A reads done before in-place update */
    if (gnext){
        stage(smb + (cur ? WB1 : WB0), gnext, nbytes, tid);
        cp_commit();
    }

#pragma unroll
    for (int mt = 0; mt < 2; mt++){
#pragma unroll
        for (int j = 0; j < NF; j++){
            int n  = wn*(8*NF) + j*8 + 2*tig;
            int r0 = wm*32 + mt*16 + gid;
            if (!LAST){
                float v0 = __sinf(W0S*(acc[mt][j][0] + sbL[n]));
                float v1 = __sinf(W0S*(acc[mt][j][1] + sbL[n+1]));
                float v2 = __sinf(W0S*(acc[mt][j][2] + sbL[n]));
                float v3 = __sinf(W0S*(acc[mt][j][3] + sbL[n+1]));
                unsigned h0 = pack_bf2(v1, v0);
                unsigned l0 = pack_bf2(v1 - bfhi(h0), v0 - bflo(h0));
                unsigned h1 = pack_bf2(v3, v2);
                unsigned l1 = pack_bf2(v3 - bfhi(h1), v2 - bflo(h1));
                unsigned off0 = (unsigned)(r0*512)     + ((((unsigned)(n>>3) ^ (unsigned)(r0 & 7))) << 4)     + (unsigned)((n & 7)*2);
                unsigned off1 = (unsigned)((r0+8)*512) + ((((unsigned)(n>>3) ^ (unsigned)((r0+8) & 7))) << 4) + (unsigned)((n & 7)*2);
                *(unsigned*)(smp + AHI + off0) = h0;
                *(unsigned*)(smp + ALO + off0) = l0;
                *(unsigned*)(smp + AHI + off1) = h1;
                *(unsigned*)(smp + ALO + off1) = l1;
            } else {
                outp[(size_t)n*P_TOT     + r0]     = acc[mt][j][0] + sbL[n];
                outp[(size_t)(n+1)*P_TOT + r0]     = acc[mt][j][1] + sbL[n+1];
                outp[(size_t)n*P_TOT     + r0 + 8] = acc[mt][j][2] + sbL[n];
                outp[(size_t)(n+1)*P_TOT + r0 + 8] = acc[mt][j][3] + sbL[n+1];
            }
        }
    }
}

__global__ void __launch_bounds__(NTHR, 2)
mlp_mma2_kernel(const float* __restrict__ feat, const float* __restrict__ times,
                const float* __restrict__ b0, const float* __restrict__ b1,
                const float* __restrict__ b2, const float* __restrict__ b3,
                const float* __restrict__ b4, const float* __restrict__ b5,
                float* __restrict__ out)
{
    extern __shared__ char smp[];
    float* sb = (float*)(smp + SBO);
    const unsigned smb = s2u(smp);
    const int tid  = threadIdx.x;
    const int wid  = tid >> 5;
    const int lane = tid & 31;
    const int wm   = wid & 1;       /* 2 M-groups (32 rows each) */
    const int wn   = wid >> 1;      /* 4 N-groups */

    const int tile = blockIdx.x;
    const int img  = tile / TPI;
    const int p0   = (tile - img*TPI) * 64;
    const int cidx = img >> 1, bidx = img & 1;
    const float tval = times[cidx];

    if (tid < 64){ sb[tid] = b0[tid]; sb[64+tid] = b1[tid]; sb[896+tid] = b5[tid]; }
    for (int i = tid; i < 256; i += NTHR){ sb[128+i] = b2[i]; sb[384+i] = b3[i]; sb[640+i] = b4[i]; }

    /* stage L0 chunk0 (4KB) */
    stage(smb + WB0, (const char*)g_w, 4096, tid);
    cp_commit();

    /* build A0 bf16 hi/lo: 64 rows x cols 0..79 (64 feats, t, zeros) */
    {
        const float* fb = feat + (size_t)(bidx*64)*P_TOT + p0;
        for (int idx = tid; idx < 5120; idx += NTHR){
            int r = idx & 63, ch = idx >> 6;
            float v = (ch < 64) ? fb[(size_t)ch*P_TOT + r] : ((ch == 64) ? tval : 0.0f);
            __nv_bfloat16 h  = __float2bfloat16(v);
            __nv_bfloat16 lo = __float2bfloat16(v - __bfloat162float(h));
            unsigned off = (unsigned)(r*512) + ((((unsigned)(ch>>3) ^ (unsigned)(r&7))) << 4) + (unsigned)((ch & 7)*2);
            *(unsigned short*)(smp + AHI + off) = *(unsigned short*)&h;
            *(unsigned short*)(smp + ALO + off) = *(unsigned short*)&lo;
        }
    }

    float* outp = out + (size_t)img*64*P_TOT + p0;
    const char* gw = (const char*)g_w;   /* byte offsets = elem offsets * 2 */
    int buf = 0;

    lay<2,false>(smb, smp, gw +      0,  5,  64, sb +   0, gw +  20480,  4096, buf, wm, wn, lane, tid, outp);
    lay<2,false>(smb, smp, gw +  20480,  4,  64, sb +  64, gw +  36864, 16384, buf, wm, wn, lane, tid, outp);
    lay<8,false>(smb, smp, gw +  36864,  4, 256, sb + 128, gw + 102400, 16384, buf, wm, wn, lane, tid, outp);
    lay<8,false>(smb, smp, gw + 102400, 16, 256, sb + 384, gw + 364544, 16384, buf, wm, wn, lane, tid, outp);
    lay<8,false>(smb, smp, gw + 364544, 16, 256, sb + 640, gw + 626688,  4096, buf, wm, wn, lane, tid, outp);
    lay<2,true >(smb, smp, gw + 626688, 16,  64, sb + 896, (const char*)0, 0,  buf, wm, wn, lane, tid, outp);
}

extern "C" void kernel_launch(void* const* d_in, const int* in_sizes, int n_in,
                              void* d_out, int out_size)
{
    const float* feat  = (const float*)d_in[0];
    const float* times = (const float*)d_in[1];
    const float* w0 = (const float*)d_in[2];
    const float* b0 = (const float*)d_in[3];
    const float* w1 = (const float*)d_in[4];
    const float* b1 = (const float*)d_in[5];
    const float* w2 = (const float*)d_in[6];
    const float* b2 = (const float*)d_in[7];
    const float* w3 = (const float*)d_in[8];
    const float* b3 = (const float*)d_in[9];
    const float* w4 = (const float*)d_in[10];
    const float* b4 = (const float*)d_in[11];
    const float* w5 = (const float*)d_in[12];
    const float* b5 = (const float*)d_in[13];
    float* out = (float*)d_out;

    cudaFuncSetAttribute(mlp_mma2_kernel, cudaFuncAttributeMaxDynamicSharedMemorySize, SMEM_TOT);

    prep_kernel<<<dim3(64, 6), 256>>>(w0, w1, w2, w3, w4, w5);
    mlp_mma2_kernel<<<NCTA, NTHR, SMEM_TOT>>>(feat, times, b0, b1, b2, b3, b4, b5, out);
}